// round 6
// baseline (speedup 1.0000x reference)
#include <cuda_runtime.h>
#include <cstdint>

#define N_NODES 50000
#define E_EDGES 1600000
#define D0 512
#define D1 256
#define D2 16

// ---------------- scratch (device globals; no allocation) ----------------
__device__ float g_X1[(size_t)N_NODES * D1];   // H @ W1
__device__ float g_X2[(size_t)N_NODES * D2];   // fused spmm+layer2 output
__device__ float g_S2[(size_t)N_NODES * D2];   // spmm(X2)
__device__ float g_Y [(size_t)N_NODES * D2];   // softmax head
__device__ float g_D [N_NODES];                // degree (weighted)
__device__ float g_Gamma[D2];
__device__ float g_W1T[(size_t)D1 * D0];       // W1 transposed: [256][512] K-major
__device__ int   g_row[E_EDGES];
__device__ int   g_col[E_EDGES];
__device__ int   g_is32;
// CSR
__device__ int   g_cnt[N_NODES];
__device__ int   g_rowptr[N_NODES + 1];
__device__ int   g_ofs[N_NODES];
__device__ unsigned long long g_edge[E_EDGES];

// ================= helpers (all arch-agnostic PTX, sm_80+) =================
__device__ __forceinline__ uint32_t smem_u32(const void* p) {
    uint32_t a;
    asm("{ .reg .u64 t; cvta.to.shared.u64 t, %1; cvt.u32.u64 %0, t; }" : "=r"(a) : "l"(p));
    return a;
}
__device__ __forceinline__ void cp_async16(uint32_t saddr, const void* g, int srcbytes) {
    asm volatile("cp.async.cg.shared.global [%0], [%1], 16, %2;"
                 :: "r"(saddr), "l"(g), "r"(srcbytes) : "memory");
}
__device__ __forceinline__ uint32_t tf32_hi(float a) {
    uint32_t r;
    asm("cvt.rna.tf32.f32 %0, %1;" : "=r"(r) : "f"(a));
    return r;
}
__device__ __forceinline__ void mma_tf32(float* c, const uint32_t* a, const uint32_t* b) {
    asm volatile(
        "mma.sync.aligned.m16n8k8.row.col.f32.tf32.tf32.f32 "
        "{%0,%1,%2,%3}, {%4,%5,%6,%7}, {%8,%9}, {%0,%1,%2,%3};"
        : "+f"(c[0]), "+f"(c[1]), "+f"(c[2]), "+f"(c[3])
        : "r"(a[0]), "r"(a[1]), "r"(a[2]), "r"(a[3]), "r"(b[0]), "r"(b[1]));
}

// ---------------- index dtype detection ----------------
__global__ void detect_idx_kernel(const void* ei) {
    const long long* p = (const long long*)ei;
    int bad = 0;
    for (int i = 0; i < 64; i++) {
        long long v = p[i];
        if (v < 0 || v >= N_NODES) bad = 1;
    }
    g_is32 = bad;
}

__global__ void convert_idx_kernel(const void* ei, int E) {
    int e = blockIdx.x * blockDim.x + threadIdx.x;
    if (e >= E) return;
    int is32 = g_is32;
    int r, c;
    if (is32) {
        const int* p = (const int*)ei;
        r = p[e]; c = p[E + e];
    } else {
        const long long* p = (const long long*)ei;
        r = (int)p[e]; c = (int)p[E + e];
    }
    g_row[e] = r;
    g_col[e] = c;
    atomicAdd(&g_cnt[r], 1);
}

__global__ void scan_kernel(int N, int E) {
    __shared__ int wsum[32];
    int tid = threadIdx.x;
    const int chunk = (N + 1023) / 1024;
    int start = tid * chunk;
    int end = min(start + chunk, N);
    int s = 0;
    for (int i = start; i < end; i++) s += g_cnt[i];
    int lane = tid & 31, wid = tid >> 5;
    int v = s;
    #pragma unroll
    for (int off = 1; off < 32; off <<= 1) {
        int t = __shfl_up_sync(0xFFFFFFFFu, v, off);
        if (lane >= off) v += t;
    }
    if (lane == 31) wsum[wid] = v;
    __syncthreads();
    if (wid == 0) {
        int w = wsum[lane];
        #pragma unroll
        for (int off = 1; off < 32; off <<= 1) {
            int t = __shfl_up_sync(0xFFFFFFFFu, w, off);
            if (lane >= off) w += t;
        }
        wsum[lane] = w;
    }
    __syncthreads();
    int excl = v - s + (wid > 0 ? wsum[wid - 1] : 0);
    int run = excl;
    for (int i = start; i < end; i++) {
        g_rowptr[i] = run;
        g_ofs[i] = run;
        run += g_cnt[i];
    }
    if (tid == 1023) g_rowptr[N] = E;
}

__global__ void scatter_kernel(const float* __restrict__ w, int E) {
    int e = blockIdx.x * blockDim.x + threadIdx.x;
    if (e >= E) return;
    int r = g_row[e];
    int pos = atomicAdd(&g_ofs[r], 1);
    unsigned long long packed =
        ((unsigned long long)__float_as_uint(w[e]) << 32) | (unsigned)g_col[e];
    g_edge[pos] = packed;
}

// ---------------- W1 transpose: [512][256] -> [256][512] ----------------
__global__ void transpose_w1(const float* __restrict__ W1, float* __restrict__ BT) {
    __shared__ float t[32][33];
    int x = blockIdx.x * 32 + threadIdx.x;   // n
    int y = blockIdx.y * 32 + threadIdx.y;   // k
    #pragma unroll
    for (int j = 0; j < 32; j += 8)
        t[threadIdx.y + j][threadIdx.x] = W1[(size_t)(y + j) * D1 + x];
    __syncthreads();
    int x2 = blockIdx.y * 32 + threadIdx.x;  // k
    int y2 = blockIdx.x * 32 + threadIdx.y;  // n
    #pragma unroll
    for (int j = 0; j < 32; j += 8)
        BT[(size_t)(y2 + j) * D0 + x2] = t[threadIdx.x][threadIdx.y + j];
}

// ---------------- GEMM1: mma.sync tf32, 3-pass split precision ----------------
#define BK 16
#define AST 20

__global__ void __launch_bounds__(256, 1)
gemm1_mma_kernel(const float* __restrict__ A, const float* __restrict__ BT,
                 float* __restrict__ C, int M) {
    __shared__ float As[2][128 * AST];
    __shared__ float Bs[2][128 * AST];

    int tid = threadIdx.x;
    int lane = tid & 31, wid = tid >> 5;
    int gid = lane >> 2, tig = lane & 3;
    int warp_m = (wid & 1) * 64;
    int warp_n = (wid >> 1) * 32;
    int row0 = blockIdx.y * 128;
    int col0 = blockIdx.x * 128;

    int lr = tid >> 2;
    int lc = (tid & 3) * 4;

    float acc[4][4][4] = {};

    const int NI = D0 / BK;

    auto load_stage = [&](int s, int i) {
        int k0 = i * BK;
        #pragma unroll
        for (int h = 0; h < 2; h++) {
            int r = lr + h * 64;
            int gr = row0 + r;
            cp_async16(smem_u32(&As[s][r * AST + lc]),
                       A + (size_t)gr * D0 + k0 + lc, gr < M ? 16 : 0);
        }
        #pragma unroll
        for (int h = 0; h < 2; h++) {
            int n = lr + h * 64;
            cp_async16(smem_u32(&Bs[s][n * AST + lc]),
                       BT + (size_t)(col0 + n) * D0 + k0 + lc, 16);
        }
    };

    load_stage(0, 0);
    asm volatile("cp.async.commit_group;");

    for (int i = 0; i < NI; i++) {
        int s = i & 1;
        if (i + 1 < NI) {
            load_stage((i + 1) & 1, i + 1);
            asm volatile("cp.async.commit_group;");
            asm volatile("cp.async.wait_group 1;");
        } else {
            asm volatile("cp.async.wait_group 0;");
        }
        __syncthreads();

        #pragma unroll
        for (int ks = 0; ks < 2; ks++) {
            int k0 = ks * 8;
            float a[4][4], b[4][2];
            #pragma unroll
            for (int t = 0; t < 4; t++) {
                int rb = warp_m + t * 16 + gid;
                a[t][0] = As[s][(rb)     * AST + k0 + tig];
                a[t][1] = As[s][(rb + 8) * AST + k0 + tig];
                a[t][2] = As[s][(rb)     * AST + k0 + tig + 4];
                a[t][3] = As[s][(rb + 8) * AST + k0 + tig + 4];
            }
            #pragma unroll
            for (int u = 0; u < 4; u++) {
                int nb = warp_n + u * 8 + gid;
                b[u][0] = Bs[s][nb * AST + k0 + tig];
                b[u][1] = Bs[s][nb * AST + k0 + tig + 4];
            }

            uint32_t ah[4][4], al[4][4], bh[4][2], bl[4][2];
            #pragma unroll
            for (int t = 0; t < 4; t++)
                #pragma unroll
                for (int q = 0; q < 4; q++) {
                    ah[t][q] = tf32_hi(a[t][q]);
                    al[t][q] = tf32_hi(a[t][q] - __uint_as_float(ah[t][q]));
                }
            #pragma unroll
            for (int u = 0; u < 4; u++)
                #pragma unroll
                for (int q = 0; q < 2; q++) {
                    bh[u][q] = tf32_hi(b[u][q]);
                    bl[u][q] = tf32_hi(b[u][q] - __uint_as_float(bh[u][q]));
                }

            #pragma unroll
            for (int t = 0; t < 4; t++)
                #pragma unroll
                for (int u = 0; u < 4; u++)
                    mma_tf32(acc[t][u], ah[t], bh[u]);
            #pragma unroll
            for (int t = 0; t < 4; t++)
                #pragma unroll
                for (int u = 0; u < 4; u++)
                    mma_tf32(acc[t][u], ah[t], bl[u]);
            #pragma unroll
            for (int t = 0; t < 4; t++)
                #pragma unroll
                for (int u = 0; u < 4; u++)
                    mma_tf32(acc[t][u], al[t], bh[u]);
        }
        __syncthreads();
    }

    #pragma unroll
    for (int t = 0; t < 4; t++) {
        int r_lo = row0 + warp_m + t * 16 + gid;
        int r_hi = r_lo + 8;
        #pragma unroll
        for (int u = 0; u < 4; u++) {
            int cc = col0 + warp_n + u * 8 + tig * 2;
            if (r_lo < M)
                *(float2*)(C + (size_t)r_lo * D1 + cc) =
                    make_float2(acc[t][u][0], acc[t][u][1]);
            if (r_hi < M)
                *(float2*)(C + (size_t)r_hi * D1 + cc) =
                    make_float2(acc[t][u][2], acc[t][u][3]);
        }
    }
}

// ---------------- FUSED SpMM d=256 + layer2 ----------------
// Per row (64 threads): S1row = segsum(w * X1[col]);
// then X2[row] = relu(S1row + b1) @ W2 via shuffle reduce. No S1 materialized.
__global__ void spmm256_layer2_kernel(const float* __restrict__ X,
                                      const float* __restrict__ b1,
                                      const float* __restrict__ W2,
                                      float* __restrict__ X2, int N) {
    __shared__ float sW[D1 * D2];   // 16 KB [k][j]
    __shared__ float sb[D1];
    __shared__ float sred[4][D2];
    for (int i = threadIdx.x; i < D1 * D2; i += 256) sW[i] = W2[i];
    for (int i = threadIdx.x; i < D1; i += 256) sb[i] = b1[i];
    __syncthreads();

    int rg = threadIdx.x >> 6;               // row group 0..3
    int row = blockIdx.x * 4 + rg;
    int lane = threadIdx.x & 63;
    bool valid = row < N;

    float4 acc = make_float4(0.f, 0.f, 0.f, 0.f);
    if (valid) {
        int beg = g_rowptr[row];
        int end = g_rowptr[row + 1];
        int e = beg;
        for (; e + 4 <= end; e += 4) {
            #pragma unroll
            for (int u = 0; u < 4; u++) {
                unsigned long long p = g_edge[e + u];
                int c = (int)(p & 0xFFFFFFFFull);
                float v = __uint_as_float((unsigned)(p >> 32));
                float4 x = *(const float4*)(X + (size_t)c * D1 + lane * 4);
                acc.x = fmaf(v, x.x, acc.x);
                acc.y = fmaf(v, x.y, acc.y);
                acc.z = fmaf(v, x.z, acc.z);
                acc.w = fmaf(v, x.w, acc.w);
            }
        }
        for (; e < end; e++) {
            unsigned long long p = g_edge[e];
            int c = (int)(p & 0xFFFFFFFFull);
            float v = __uint_as_float((unsigned)(p >> 32));
            float4 x = *(const float4*)(X + (size_t)c * D1 + lane * 4);
            acc.x = fmaf(v, x.x, acc.x);
            acc.y = fmaf(v, x.y, acc.y);
            acc.z = fmaf(v, x.z, acc.z);
            acc.w = fmaf(v, x.w, acc.w);
        }
    }

    // bias + relu + partial W2 contraction (4 ks per thread)
    int k0 = lane * 4;
    float h0 = fmaxf(acc.x + sb[k0 + 0], 0.f);
    float h1 = fmaxf(acc.y + sb[k0 + 1], 0.f);
    float h2 = fmaxf(acc.z + sb[k0 + 2], 0.f);
    float h3 = fmaxf(acc.w + sb[k0 + 3], 0.f);
    float p[D2];
    #pragma unroll
    for (int j = 0; j < D2; j++) {
        p[j] = fmaf(h0, sW[(k0 + 0) * D2 + j],
               fmaf(h1, sW[(k0 + 1) * D2 + j],
               fmaf(h2, sW[(k0 + 2) * D2 + j],
                    h3 * sW[(k0 + 3) * D2 + j])));
    }
    // intra-warp reduce (32 lanes)
    #pragma unroll
    for (int off = 16; off > 0; off >>= 1)
        #pragma unroll
        for (int j = 0; j < D2; j++)
            p[j] += __shfl_down_sync(0xFFFFFFFFu, p[j], off);
    // cross-warp (2 warps per row) via smem
    int wInRow = lane >> 5;
    if ((lane & 31) == 0 && wInRow == 1) {
        #pragma unroll
        for (int j = 0; j < D2; j++) sred[rg][j] = p[j];
    }
    __syncthreads();
    if ((lane & 31) == 0 && wInRow == 0 && valid) {
        float* o = X2 + (size_t)row * D2;
        #pragma unroll
        for (int q = 0; q < 4; q++) {
            *(float4*)(o + q * 4) = make_float4(
                p[q * 4 + 0] + sred[rg][q * 4 + 0],
                p[q * 4 + 1] + sred[rg][q * 4 + 1],
                p[q * 4 + 2] + sred[rg][q * 4 + 2],
                p[q * 4 + 3] + sred[rg][q * 4 + 3]);
        }
    }
}

// ---------------- SpMM d=16 + degree (CSR) ----------------
__global__ void spmm16_csr_kernel(const float* __restrict__ X2,
                                  float* __restrict__ S2, float* __restrict__ D, int N) {
    int row = blockIdx.x * 16 + (threadIdx.x >> 4);
    if (row >= N) return;
    int j = threadIdx.x & 15;
    int beg = g_rowptr[row];
    int end = g_rowptr[row + 1];

    float acc = 0.f, wsum = 0.f;
    for (int e = beg; e < end; e++) {
        unsigned long long p = g_edge[e];
        int c = (int)(p & 0xFFFFFFFFull);
        float v = __uint_as_float((unsigned)(p >> 32));
        acc = fmaf(v, X2[(size_t)c * D2 + j], acc);
        wsum += v;
    }
    S2[(size_t)row * D2 + j] = acc;
    if (j == 0) D[row] = wsum;
}

// ---------------- head ----------------
__global__ void head_kernel(const float* __restrict__ S2, const float* __restrict__ b2,
                            const float* __restrict__ Wl, const float* __restrict__ bl,
                            const float* __restrict__ D, float* __restrict__ Y,
                            float* __restrict__ Gamma, int N) {
    __shared__ float sW[D2 * D2];
    __shared__ float sb2[D2];
    __shared__ float sbl[D2];
    __shared__ float sG[D2];
    if (threadIdx.x < D2 * D2) sW[threadIdx.x] = Wl[threadIdx.x];
    if (threadIdx.x < D2) {
        sb2[threadIdx.x] = b2[threadIdx.x];
        sbl[threadIdx.x] = bl[threadIdx.x];
        sG[threadIdx.x] = 0.f;
    }
    __syncthreads();

    int row = blockIdx.x * blockDim.x + threadIdx.x;
    if (row < N) {
        float h2[D2];
        const float4* s = (const float4*)(S2 + (size_t)row * D2);
        #pragma unroll
        for (int q = 0; q < 4; q++) {
            float4 v = s[q];
            h2[q * 4 + 0] = fmaxf(v.x + sb2[q * 4 + 0], 0.f);
            h2[q * 4 + 1] = fmaxf(v.y + sb2[q * 4 + 1], 0.f);
            h2[q * 4 + 2] = fmaxf(v.z + sb2[q * 4 + 2], 0.f);
            h2[q * 4 + 3] = fmaxf(v.w + sb2[q * 4 + 3], 0.f);
        }
        float h3[D2];
        #pragma unroll
        for (int j = 0; j < D2; j++) {
            float t = sbl[j];
            #pragma unroll
            for (int k = 0; k < D2; k++) t = fmaf(h2[k], sW[k * D2 + j], t);
            h3[j] = fmaxf(t, 0.f);
        }
        float m = h3[0];
        #pragma unroll
        for (int j = 1; j < D2; j++) m = fmaxf(m, h3[j]);
        float sum = 0.f;
        float y[D2];
        #pragma unroll
        for (int j = 0; j < D2; j++) { y[j] = __expf(h3[j] - m); sum += y[j]; }
        float inv = 1.0f / sum;
        float4* o = (float4*)(Y + (size_t)row * D2);
        #pragma unroll
        for (int q = 0; q < 4; q++) {
            o[q] = make_float4(y[q * 4 + 0] * inv, y[q * 4 + 1] * inv,
                               y[q * 4 + 2] * inv, y[q * 4 + 3] * inv);
        }
        float d = D[row];
        #pragma unroll
        for (int j = 0; j < D2; j++) atomicAdd(&sG[j], y[j] * inv * d);
    }
    __syncthreads();
    if (threadIdx.x < D2) atomicAdd(&Gamma[threadIdx.x], sG[threadIdx.x]);
}

// ---------------- loss ----------------
__global__ void loss_kernel(const int* __restrict__ ridx,
                            const int* __restrict__ cidx,
                            const float* __restrict__ w,
                            const float* __restrict__ Y,
                            const float* __restrict__ Gamma,
                            float* __restrict__ out, int E) {
    __shared__ float sGinv[D2];
    if (threadIdx.x < D2) sGinv[threadIdx.x] = 1.0f / Gamma[threadIdx.x];
    __syncthreads();

    int e = blockIdx.x * blockDim.x + threadIdx.x;
    float acc = 0.f;
    if (e < E) {
        int r = ridx[e];
        int c = cidx[e];
        float v = w[e];
        const float4* yr = (const float4*)(Y + (size_t)r * D2);
        const float4* yc = (const float4*)(Y + (size_t)c * D2);
        #pragma unroll
        for (int q = 0; q < 4; q++) {
            float4 a = yr[q];
            float4 b = yc[q];
            acc += a.x * sGinv[q * 4 + 0] * (1.f - b.x)
                 + a.y * sGinv[q * 4 + 1] * (1.f - b.y)
                 + a.z * sGinv[q * 4 + 2] * (1.f - b.z)
                 + a.w * sGinv[q * 4 + 3] * (1.f - b.w);
        }
        acc *= v;
    }
    #pragma unroll
    for (int off = 16; off > 0; off >>= 1)
        acc += __shfl_down_sync(0xFFFFFFFFu, acc, off);
    if ((threadIdx.x & 31) == 0) atomicAdd(out, acc);
}

// ---------------- launch ----------------
extern "C" void kernel_launch(void* const* d_in, const int* in_sizes, int n_in,
                              void* d_out, int out_size) {
    const float*     H    = (const float*)d_in[0];
    const void*      ei   = d_in[1];
    const float*     ev   = (const float*)d_in[2];
    const float*     W1   = (const float*)d_in[3];
    const float*     b1   = (const float*)d_in[4];
    const float*     W2   = (const float*)d_in[5];
    const float*     b2   = (const float*)d_in[6];
    const float*     Wl   = (const float*)d_in[7];
    const float*     bl   = (const float*)d_in[8];
    float* out = (float*)d_out;

    int N = in_sizes[0] / D0;          // 50000
    int E = in_sizes[2];               // 1600000

    void *pX1, *pX2, *pS2, *pY, *pD, *pG, *pR, *pC, *pCnt, *pW1T;
    cudaGetSymbolAddress(&pX1, g_X1);
    cudaGetSymbolAddress(&pX2, g_X2);
    cudaGetSymbolAddress(&pS2, g_S2);
    cudaGetSymbolAddress(&pY,  g_Y);
    cudaGetSymbolAddress(&pD,  g_D);
    cudaGetSymbolAddress(&pG,  g_Gamma);
    cudaGetSymbolAddress(&pR,  g_row);
    cudaGetSymbolAddress(&pC,  g_col);
    cudaGetSymbolAddress(&pCnt, g_cnt);
    cudaGetSymbolAddress(&pW1T, g_W1T);
    const int* ridx = (const int*)pR;
    const int* cidx = (const int*)pC;

    // one-time stream/event setup (outside capture: first call is the
    // correctness run, not captured; no device memory allocated here)
    static cudaStream_t s_side = nullptr;
    static cudaEvent_t ev_fork = nullptr, ev_join = nullptr;
    if (s_side == nullptr) {
        cudaStreamCreateWithFlags(&s_side, cudaStreamNonBlocking);
        cudaEventCreateWithFlags(&ev_fork, cudaEventDisableTiming);
        cudaEventCreateWithFlags(&ev_join, cudaEventDisableTiming);
    }

    // ---- main stream: small zero-inits ----
    cudaMemsetAsync(pG,  0, D2 * sizeof(float));
    cudaMemsetAsync(out, 0, sizeof(float));

    // ---- fork side stream: CSR build (independent of GEMM) ----
    cudaEventRecord(ev_fork, 0);
    cudaStreamWaitEvent(s_side, ev_fork, 0);
    cudaMemsetAsync(pCnt, 0, N_NODES * sizeof(int), s_side);
    detect_idx_kernel<<<1, 1, 0, s_side>>>(ei);
    convert_idx_kernel<<<(E + 255) / 256, 256, 0, s_side>>>(ei, E);
    scan_kernel<<<1, 1024, 0, s_side>>>(N, E);
    scatter_kernel<<<(E + 255) / 256, 256, 0, s_side>>>(ev, E);
    cudaEventRecord(ev_join, s_side);

    // ---- main stream: transpose + GEMM (concurrent with CSR build) ----
    transpose_w1<<<dim3(D1 / 32, D0 / 32), dim3(32, 8)>>>(W1, (float*)pW1T);
    {
        dim3 grid(D1 / 128, (N + 127) / 128);
        gemm1_mma_kernel<<<grid, 256>>>(H, (const float*)pW1T, (float*)pX1, N);
    }

    // ---- join: everything below needs both CSR and X1 ----
    cudaStreamWaitEvent(0, ev_join, 0);

    // 2+3) fused: X2 = relu(spmm(X1) + b1) @ W2
    spmm256_layer2_kernel<<<(N + 3) / 4, 256>>>((const float*)pX1, b1, W2,
                                                (float*)pX2, N);
    // 4) S2 = spmm(X2), D = degree
    spmm16_csr_kernel<<<(N + 15) / 16, 256>>>((const float*)pX2, (float*)pS2, (float*)pD, N);
    // 5) head
    head_kernel<<<(N + 255) / 256, 256>>>((const float*)pS2, b2, Wl, bl,
                                          (const float*)pD, (float*)pY, (float*)pG, N);
    // 6) loss
    loss_kernel<<<(E + 255) / 256, 256>>>(ridx, cidx, ev, (const float*)pY,
                                          (const float*)pG, out, E);
}